// round 1
// baseline (speedup 1.0000x reference)
#include <cuda_runtime.h>
#include <math.h>

// Problem constants (shapes fixed by the reference)
#define NQ      1024      // batch B
#define LQ      128       // seq len L
#define KPOS    8         // positives per row
#define NNEG    2048      // negatives
#define NLABPOS 8192      // NQ*KPOS
#define NW      10240     // 8192 label rows + 2048 neg rows
#define NR      11264     // NQ + NW feature rows
#define DIM     256
#define NHEAD   4
#define HDIM    64
#define NP      16        // anchors
#define NM      32        // PRF features per quad node
#define NLAB    131072

// ---------------- device scratch (no allocation allowed) ----------------
__device__ __align__(16) float g_raw[NR * DIM];        // raw 256-d vectors (queries then W rows)
__device__ __align__(16) float g_poly[NR * NHEAD * NP];   // [row][h][p]
__device__ __align__(16) float g_prf [NR * NHEAD * 64];   // [row][h][r*32+m]
__device__ float g_G[NHEAD * NP * 64];                 // [h][p][m']
__device__ float g_acc[2];                             // {numerator, denominator}
__device__ float g_anorm[NP];                          // 1/||anchor_p||

// ---------------- quadrature / scaling constants -----------------------
__device__ __forceinline__ void slay_consts(float s[2], float sq2s[2], float emult[2]) {
    const double R2 = 1.4142135623730951;
    const double C  = 2.000001;
    double n0 = (2.0 - R2) / C, n1 = (2.0 + R2) / C;
    double w0 = ((2.0 + R2) / 4.0) / C, w1 = ((2.0 - R2) / 4.0) / C;
    s[0] = (float)n0; s[1] = (float)n1;
    sq2s[0] = sqrtf(2.0f * s[0]); sq2s[1] = sqrtf(2.0f * s[1]);
    float invSqM = (float)(1.0 / sqrt(32.000001));   // 1/sqrt(M + 1e-6)
    emult[0] = invSqM * (float)sqrt(w0);
    emult[1] = invSqM * (float)sqrt(w1);
}

// ---------------- K0: init -------------------------------------------------
__global__ void k0_init(const float* __restrict__ anchors) {
    int t = threadIdx.x;  // 1024 threads, 1 block
    for (int i = t; i < NHEAD * NP * 64; i += 1024) g_G[i] = 0.f;
    if (t < 2) g_acc[t] = 0.f;
    if (t < NP) {
        float s = 0.f;
        #pragma unroll 8
        for (int d = 0; d < HDIM; ++d) { float v = anchors[t * HDIM + d]; s += v * v; }
        g_anorm[t] = 1.f / sqrtf(s);   // reference: anchors / norm (no eps)
    }
}

// ---------------- K1: masked-mean query embedding -------------------------
__global__ void k1_query(const int* __restrict__ idx, const float* __restrict__ mask,
                         const float* __restrict__ table) {
    int b = blockIdx.x;        // 1024
    int t = threadIdx.x;       // 256
    __shared__ int   sIdx[LQ];
    __shared__ float sMask[LQ];
    __shared__ float sRed[256];
    if (t < LQ) { sIdx[t] = idx[b * LQ + t]; sMask[t] = mask[b * LQ + t]; }
    __syncthreads();
    sRed[t] = (t < LQ) ? sMask[t] : 0.f;
    __syncthreads();
    for (int s = 128; s > 0; s >>= 1) { if (t < s) sRed[t] += sRed[t + s]; __syncthreads(); }
    float inv = 1.f / fmaxf(sRed[0], 1.f);
    float acc = 0.f;
    #pragma unroll 4
    for (int l = 0; l < LQ; ++l)
        acc += table[(size_t)sIdx[l] * DIM + t] * sMask[l];
    g_raw[b * DIM + t] = acc * inv;
}

// ---------------- K1b: gather W columns (kernel.T rows) -------------------
__global__ void k1b_gatherW(const int* __restrict__ labels, const int* __restrict__ negidx,
                            const float* __restrict__ kmat) {
    int j = blockIdx.x;        // 10240
    int t = threadIdx.x;       // 256
    int col = (j < NLABPOS) ? max(labels[j], 0) : negidx[j - NLABPOS];
    g_raw[(size_t)(NQ + j) * DIM + t] = __ldg(&kmat[(size_t)t * NLAB + col]);
}

// ---------------- K2: normalize + features --------------------------------
#define RPB 32
#define TPB2 320
__global__ void k2_features(const float* __restrict__ omega, const float* __restrict__ anchors) {
    __shared__ float zs[RPB * DIM];     // 32 KB
    __shared__ float ssq[RPB * NHEAD];
    __shared__ float scal[RPB * NHEAD];
    int t = threadIdx.x;
    int row0 = blockIdx.x * RPB;

    // coalesced load of 32 rows (vectorized)
    const float4* src = (const float4*)(g_raw + (size_t)row0 * DIM);
    float4* dst = (float4*)zs;
    for (int i = t; i < RPB * DIM / 4; i += TPB2) dst[i] = src[i];
    __syncthreads();

    // per-(row, head) sum of squares
    if (t < RPB * NHEAD) {
        int rr = t >> 2, h = t & 3;
        const float* z = &zs[rr * DIM + h * HDIM];
        float s = 0.f;
        #pragma unroll 8
        for (int d = 0; d < HDIM; ++d) s += z[d] * z[d];
        ssq[t] = s;
    }
    __syncthreads();
    // combined full + per-head normalization scale (matches safe_normalize twice)
    if (t < RPB) {
        float s0 = ssq[t*4], s1 = ssq[t*4+1], s2 = ssq[t*4+2], s3 = ssq[t*4+3];
        float invf = 1.f / fmaxf(sqrtf(s0 + s1 + s2 + s3), 1e-4f);
        float sh[4] = {s0, s1, s2, s3};
        #pragma unroll
        for (int h = 0; h < 4; ++h) {
            float nh = sqrtf(sh[h]) * invf;               // ||y_h|| after full normalize
            scal[t*4 + h] = invf / fmaxf(nh, 1e-4f);
        }
    }
    __syncthreads();

    float sC[2], sq2s[2], emult[2];
    slay_consts(sC, sq2s, emult);

    // thread t -> (head h, output u): u<16 poly_p, else prf (r,m)
    int h = t / 80;
    int u = t - h * 80;
    bool isPoly = (u < 16);
    int q = u - 16;                // prf index in [0,64)
    int r = (q >> 5) & 1;
    const float* wptr;
    int wstride;
    if (isPoly) { wptr = anchors + u * HDIM;                         wstride = 1; }
    else        { wptr = omega + (size_t)((r*4 + h) * HDIM) * NM + (q & 31); wstride = NM; }

    for (int c0 = 0; c0 < RPB; c0 += 8) {
        float acc[8] = {0,0,0,0,0,0,0,0};
        const float* zb = &zs[c0 * DIM + h * HDIM];
        #pragma unroll 4
        for (int d = 0; d < HDIM; ++d) {
            float wv = __ldg(wptr + d * wstride);
            #pragma unroll
            for (int i = 0; i < 8; ++i)
                acc[i] = fmaf(wv, zb[i * DIM + d], acc[i]);
        }
        #pragma unroll
        for (int i = 0; i < 8; ++i) {
            int rr = c0 + i;
            int g  = row0 + rr;
            float sc = scal[rr * 4 + h];
            if (isPoly) {
                float v = acc[i] * sc * g_anorm[u];
                v = fminf(fmaxf(v, -1.f), 1.f);
                g_poly[(size_t)g * 64 + h * NP + u] = v * v * 0.25f;   // /sqrt(P)=4
            } else {
                float proj = acc[i] * sc * 0.125f;                     // omega/sqrt(64)
                float arg = proj * sq2s[r] - sC[r];
                arg = fminf(fmaxf(arg, -20.f), 20.f);
                g_prf[(size_t)g * 256 + h * 64 + q] = expf(arg) * emult[r];
            }
        }
    }
}

// ---------------- K3: G_h = sum over negs of poly ⊗ prf -------------------
__global__ void k3_G() {
    __shared__ float sm[32 * 320];   // 40 KB: [row][poly64 | prf256]
    int t = threadIdx.x;             // 512
    int base = NQ + NLABPOS + blockIdx.x * 32;   // 64 blocks * 32 rows = 2048 negs
    for (int i = t; i < 32 * 320; i += 512) {
        int rr = i / 320, u = i - rr * 320;
        int g = base + rr;
        sm[i] = (u < 64) ? g_poly[(size_t)g * 64 + u] : g_prf[(size_t)g * 256 + (u - 64)];
    }
    __syncthreads();
    int hp = t >> 3;            // 0..63 -> h*16+p
    int h  = hp >> 4;
    int mb = (t & 7) << 3;      // m-block of 8
    float acc[8] = {0,0,0,0,0,0,0,0};
    #pragma unroll 4
    for (int rr = 0; rr < 32; ++rr) {
        const float* row = sm + rr * 320;
        float pv = row[hp];
        const float* pr = row + 64 + h * 64 + mb;
        #pragma unroll
        for (int i = 0; i < 8; ++i) acc[i] += pv * pr[i];
    }
    #pragma unroll
    for (int i = 0; i < 8; ++i) atomicAdd(&g_G[hp * 64 + mb + i], acc[i]);
}

// ---------------- K4: per-query negSum + positives + loss terms -----------
__global__ void k4_final(const float* __restrict__ lmask) {
    int b = blockIdx.x;     // 1024
    int t = threadIdx.x;    // 256
    __shared__ float sNeg[256];
    __shared__ float sPolyQ[64];
    __shared__ float sPrfQ[256];
    if (t < 64) sPolyQ[t] = g_poly[(size_t)b * 64 + t];
    sPrfQ[t] = g_prf[(size_t)b * 256 + t];
    __syncthreads();

    // negSum = sum_h polyQ_h^T G_h prfQ_h
    int h = t >> 6, m = t & 63;
    float tv = 0.f;
    #pragma unroll
    for (int p = 0; p < NP; ++p)
        tv += sPolyQ[h * NP + p] * __ldg(&g_G[(h * NP + p) * 64 + m]);
    sNeg[t] = tv * sPrfQ[t];
    __syncthreads();
    for (int s = 128; s > 0; s >>= 1) { if (t < s) sNeg[t] += sNeg[t + s]; __syncthreads(); }
    float negSum = sNeg[0];

    // warp 0: 8 positive scores, lane = k*4 + h
    if (t < 32) {
        int k  = t >> 2;
        int hh = t & 3;
        int wrow = NQ + b * KPOS + k;
        float A = 0.f, B = 0.f;
        const float* pw = &g_poly[(size_t)wrow * 64 + hh * NP];
        const float* pq = &sPolyQ[hh * NP];
        #pragma unroll
        for (int p = 0; p < NP; ++p) A += pq[p] * __ldg(&pw[p]);
        const float* rw = &g_prf[(size_t)wrow * 256 + hh * 64];
        const float* rq = &sPrfQ[hh * 64];
        #pragma unroll 8
        for (int mm = 0; mm < 64; ++mm) B += rq[mm] * __ldg(&rw[mm]);
        float sc = A * B;
        sc += __shfl_xor_sync(0xffffffff, sc, 1);
        sc += __shfl_xor_sync(0xffffffff, sc, 2);   // every lane in k-group holds score_k

        float pall[KPOS];
        #pragma unroll
        for (int k2 = 0; k2 < KPOS; ++k2)
            pall[k2] = __shfl_sync(0xffffffff, sc, k2 * 4);

        if (t == 0) {
            float S = negSum + (float)NNEG * 1e-8f;
            #pragma unroll
            for (int k2 = 0; k2 < KPOS; ++k2) S += pall[k2] + 1e-8f;
            float logS = logf(S);
            float num = 0.f, den = 0.f;
            #pragma unroll
            for (int k2 = 0; k2 < KPOS; ++k2) {
                float lm = lmask[b * KPOS + k2];
                num += lm * (logf(pall[k2] + 1e-8f) - logS);
                den += lm;
            }
            atomicAdd(&g_acc[0], num);
            atomicAdd(&g_acc[1], den);
        }
    }
}

// ---------------- K5: scalar out ------------------------------------------
__global__ void k5_out(float* __restrict__ out) {
    out[0] = -g_acc[0] / (g_acc[1] + 1e-6f);
}

// ---------------- launch ---------------------------------------------------
extern "C" void kernel_launch(void* const* d_in, const int* in_sizes, int n_in,
                              void* d_out, int out_size) {
    const int*   indices = (const int*)  d_in[0];
    const float* mask    = (const float*)d_in[1];
    const int*   labels  = (const int*)  d_in[2];
    const float* lmask   = (const float*)d_in[3];
    const int*   negidx  = (const int*)  d_in[4];
    const float* table   = (const float*)d_in[5];
    const float* kmat    = (const float*)d_in[6];
    const float* omega   = (const float*)d_in[7];
    const float* anchors = (const float*)d_in[8];
    float* out = (float*)d_out;

    k0_init   <<<1, 1024>>>(anchors);
    k1_query  <<<NQ, 256>>>(indices, mask, table);
    k1b_gatherW<<<NW, 256>>>(labels, negidx, kmat);
    k2_features<<<NR / RPB, TPB2>>>(omega, anchors);
    k3_G      <<<NNEG / 32, 512>>>();
    k4_final  <<<NQ, 256>>>(lmask);
    k5_out    <<<1, 1>>>(out);
}